// round 15
// baseline (speedup 1.0000x reference)
#include <cuda_runtime.h>
#include <cstdint>
#include <cstddef>

// Problem constants
constexpr int Bb = 2;
constexpr int Nn = 10000;
constexpr int Kk = 20;
constexpr int NP = Bb * Nn;
constexpr int SEG = 10;
constexpr int SEGSZ = 1024;   // 9*1024 + 784 = 10000 (tail guarded)
constexpr int TQ = 128;
constexpr int QT = 2;         // queries per thread
constexpr int QB = TQ * QT;   // queries per block
constexpr int TM = 32;        // candidate tile
constexpr int PAIRS = TM / 2;
constexpr int PEND = 68;      // per-thread pending buffer (local mem)

// Scratch (device globals). Ping-pong buffers: layer L reads one, writes other.
__device__ __align__(16) float g_xTa[(size_t)NP * 128];
__device__ __align__(16) float g_xTb[(size_t)NP * 128];
__device__ float g_norma[NP];
__device__ float g_normb[NP];
__device__ float g_pd[(size_t)NP * SEG * Kk];
__device__ int   g_pi[(size_t)NP * SEG * Kk];

using u64 = unsigned long long;
__device__ __forceinline__ u64 pk2(float lo, float hi) {
    u64 r; asm("mov.b64 %0,{%1,%2};" : "=l"(r) : "f"(lo), "f"(hi)); return r;
}
__device__ __forceinline__ u64 bc2(float v) { return pk2(v, v); }
__device__ __forceinline__ void upk2(u64 v, float& lo, float& hi) {
    asm("mov.b64 {%0,%1},%2;" : "=f"(lo), "=f"(hi) : "l"(v));
}
// Packed fp32 FMA / ADD (SASS FFMA2/FADD2): two independent IEEE fp32 ops.
__device__ __forceinline__ u64 ffma2(u64 a, u64 b, u64 c) {
    u64 d; asm("fma.rn.f32x2 %0,%1,%2,%3;" : "=l"(d) : "l"(a), "l"(b), "l"(c)); return d;
}
__device__ __forceinline__ u64 fadd2(u64 a, u64 b) {
    u64 d; asm("add.rn.f32x2 %0,%1,%2;" : "=l"(d) : "l"(a), "l"(b)); return d;
}
// Predicated store: no branch (no BSSY), no L1 wavefront when acc==0.
__device__ __forceinline__ void pstore(u64* addr, u64 val, unsigned acc) {
    asm volatile("{\n\t.reg .pred p;\n\tsetp.ne.u32 p, %0, 0;\n\t@p st.u64 [%1], %2;\n\t}"
        :: "r"(acc), "l"(addr), "l"(val) : "memory");
}

// ---------------------------------------------------------------------------
// Transpose (B,C,N) -> (B,N,C) + sq-norms — used only for the network input x.
// ---------------------------------------------------------------------------
__global__ void transpose_norm_kernel(const float* __restrict__ src, int C, int batchStride,
                                      float* __restrict__ xout, float* __restrict__ normout) {
    int p = blockIdx.x * blockDim.x + threadIdx.x;
    if (p >= NP) return;
    int b = p / Nn, n = p % Nn;
    const float* s = src + (size_t)b * batchStride + n;
    float* d = xout + (size_t)p * C;
    float sum = 0.f;
    for (int c = 0; c < C; ++c) {
        float v = s[(size_t)c * Nn];
        d[c] = v;
        sum = __fadd_rn(sum, __fmul_rn(v, v));
    }
    normout[p] = sum;
}

// ---------------------------------------------------------------------------
// KNN partial pass over one candidate segment. Reference arithmetic exactly:
//   dot = ascending-c FMA chain;  pd = fsub(fsub(-xxq, -2*dot), xxm)
//   (packed: fma2(2,dot,negqn) [bitwise == since -2*dot exact] + add2(.,-mn))
// top-k LARGEST pd, tie -> lower index. Sorted smem lists; register threshold.
// Epilogue: PREDICATED pending append; one batched drain per tile (FIFO +
// strict > + drain-time recheck => exact lax.top_k). CH=4 keeps qv2 register
// block small => 5 resident blocks/SM; SEG=10 => grid 800 keeps them fed.
// ---------------------------------------------------------------------------
template <int C>
__global__ void __launch_bounds__(TQ, 5) knn_part_kernel(const float* __restrict__ xin,
                                                         const float* __restrict__ norm) {
    __shared__ __align__(16) float ms2[TM * C];     // [pair][c][2]
    __shared__ u64 s_negmn2[PAIRS];                 // packed -norm pairs
    __shared__ float s_bd[QT][Kk][TQ];
    __shared__ unsigned short s_bi[QT][Kk][TQ];

    u64 pend[PEND];                                  // local mem (L1-resident)

    int b = blockIdx.z, seg = blockIdx.y;
    int t = threadIdx.x;
    const float* xb = xin + (size_t)b * Nn * C;

    int q[QT]; bool act[QT]; const float* qrow[QT]; u64 negqn2[QT]; float kth[QT];
#pragma unroll
    for (int s = 0; s < QT; ++s) {
        q[s] = blockIdx.x * QB + s * TQ + t;
        act[s] = q[s] < Nn;
        qrow[s] = xb + (size_t)(act[s] ? q[s] : 0) * C;
        negqn2[s] = bc2(act[s] ? -norm[b * Nn + q[s]] : 0.f);
        kth[s] = act[s] ? -3.4e38f : 3.4e38f;   // inactive never accepts
#pragma unroll
        for (int k = 0; k < Kk; ++k) { s_bd[s][k][t] = -3.4e38f; s_bi[s][k][t] = 0; }
    }
    int cnt = 0;
    const u64 TWO2 = bc2(2.f);

    auto drain = [&]() {
#pragma unroll 1
        for (int i = 0; i < cnt; ++i) {
            float pdv, mf;
            upk2(pend[i], pdv, mf);
            unsigned m = __float_as_uint(mf);
            int s = (int)(m >> 15);
            unsigned short idx = (unsigned short)(m & 0x7FFFu);
            float kk = (s == 0) ? kth[0] : kth[1];
            if (pdv > kk) {
                int j = Kk - 1;
#pragma unroll 1
                while (j > 0) {
                    float prev = s_bd[s][j - 1][t];
                    if (pdv > prev) {
                        s_bd[s][j][t] = prev;
                        s_bi[s][j][t] = s_bi[s][j - 1][t];
                        --j;
                    } else break;
                }
                s_bd[s][j][t] = pdv;
                s_bi[s][j][t] = idx;
                if (s == 0) kth[0] = s_bd[0][Kk - 1][t];
                else        kth[1] = s_bd[1][Kk - 1][t];
            }
        }
        cnt = 0;
    };

    int mt0 = seg * SEGSZ;
    int mt1 = min(Nn, mt0 + SEGSZ);

#pragma unroll 1
    for (int mt = mt0; mt < mt1; mt += TM) {
        __syncthreads();
        for (int i = t; i < PAIRS * (C / 4); i += TQ) {
            int p8 = i / (C / 4), c4 = i % (C / 4);
            int r0 = min(mt + 2 * p8, Nn - 1);
            int r1 = min(mt + 2 * p8 + 1, Nn - 1);
            float4 a = ((const float4*)(xb + (size_t)r0 * C))[c4];
            float4 v = ((const float4*)(xb + (size_t)r1 * C))[c4];
            float* dst = ms2 + p8 * 2 * C + 8 * c4;
            ((float4*)dst)[0] = make_float4(a.x, v.x, a.y, v.y);
            ((float4*)dst)[1] = make_float4(a.z, v.z, a.w, v.w);
        }
        if (t < PAIRS)
            s_negmn2[t] = pk2(-norm[b * Nn + min(mt + 2 * t, Nn - 1)],
                              -norm[b * Nn + min(mt + 2 * t + 1, Nn - 1)]);
        __syncthreads();

        u64 part2[QT][PAIRS];
#pragma unroll
        for (int s = 0; s < QT; ++s)
#pragma unroll
            for (int p = 0; p < PAIRS; ++p) part2[s][p] = 0ull;

        constexpr int CH = (C < 4) ? C : 4;
#pragma unroll 1
        for (int cc = 0; cc < C; cc += CH) {
            u64 qv2[QT][CH];
#pragma unroll
            for (int s = 0; s < QT; ++s) {
                float4 v = *(const float4*)(qrow[s] + cc);
                qv2[s][0] = bc2(v.x); qv2[s][1] = bc2(v.y);
                qv2[s][2] = bc2(v.z); qv2[s][3] = bc2(v.w);
            }
#pragma unroll
            for (int p = 0; p < PAIRS; ++p) {
                const ulonglong2* src = (const ulonglong2*)(ms2 + p * 2 * C + 2 * cc);
                ulonglong2 v = src[0];
#pragma unroll
                for (int s = 0; s < QT; ++s) {
                    part2[s][p] = ffma2(qv2[s][0], v.x, part2[s][p]);
                    part2[s][p] = ffma2(qv2[s][1], v.y, part2[s][p]);
                }
                ulonglong2 v2 = src[1];
#pragma unroll
                for (int s = 0; s < QT; ++s) {
                    part2[s][p] = ffma2(qv2[s][2], v2.x, part2[s][p]);
                    part2[s][p] = ffma2(qv2[s][3], v2.y, part2[s][p]);
                }
            }
        }

        // epilogue: predicated append (no branch, no store traffic on reject)
#pragma unroll
        for (int p = 0; p < PAIRS; ++p) {
            u64 nm = s_negmn2[p];
            int cidx = mt + 2 * p;
#pragma unroll
            for (int s = 0; s < QT; ++s) {
                u64 pd2 = fadd2(ffma2(TWO2, part2[s][p], negqn2[s]), nm);
                float p0, p1;
                upk2(pd2, p0, p1);
                unsigned m0 = ((unsigned)s << 15) | (unsigned)cidx;
                unsigned a0 = (p0 > kth[s] && cidx < mt1) ? 1u : 0u;
                pstore(pend + cnt, pk2(p0, __uint_as_float(m0)), a0);
                cnt += a0;
                unsigned a1 = (p1 > kth[s] && cidx + 1 < mt1) ? 1u : 0u;
                pstore(pend + cnt, pk2(p1, __uint_as_float(m0 + 1)), a1);
                cnt += a1;
            }
        }
        if (__ballot_sync(0xFFFFFFFFu, cnt > 0)) drain();
    }

#pragma unroll
    for (int s = 0; s < QT; ++s) {
        if (!act[s]) continue;
        size_t base = ((size_t)(b * Nn + q[s]) * SEG + seg) * Kk;
#pragma unroll
        for (int k = 0; k < Kk; ++k) {
            g_pd[base + k] = s_bd[s][k][t];
            g_pi[base + k] = (int)s_bi[s][k][t];
        }
    }
}

// ---------------------------------------------------------------------------
// EdgeConv + fused KNN-merge + fused transpose/norm for the next layer.
// xin != xout (ping-pong) => no same-launch RAW hazard.
// ---------------------------------------------------------------------------
template <int CIN, int COUT, int PG, bool WXT>
__global__ void edgeconv_kernel(const float* __restrict__ w,
                                const float* __restrict__ gg,
                                const float* __restrict__ bbias,
                                const float* __restrict__ mmean,
                                const float* __restrict__ vvar,
                                float* __restrict__ out, int coff,
                                const float* __restrict__ xin,
                                float* __restrict__ xout,
                                float* __restrict__ normout) {
    constexpr int PT = 4;
    constexpr int PPB = PT * PG;
    constexpr int THREADS = COUT * PG;
    constexpr int K2 = Kk / 2;

    __shared__ __align__(16) float s_dnb2[PPB * K2 * CIN * 2];  // [p][j][c][2]
    __shared__ __align__(16) float s_ctr[PPB][CIN];
    __shared__ int s_idx[PPB][Kk];
    __shared__ float s_yout[WXT ? PPB * COUT : 1];

    int p0 = blockIdx.x * PPB;
    int t = threadIdx.x;

    // fused merge: one thread per point combines SEG sorted 20-lists
    if (t < PPB) {
        float bd[Kk]; int bi[Kk];
#pragma unroll
        for (int i = 0; i < Kk; ++i) { bd[i] = -3.4e38f; bi[i] = 0; }
        size_t base = (size_t)(p0 + t) * SEG * Kk;
#pragma unroll 1
        for (int e = 0; e < SEG * Kk; ++e) {
            float pdv = g_pd[base + e];
            int idx = g_pi[base + e];
            if (pdv > bd[Kk - 1]) {
                bd[Kk - 1] = pdv; bi[Kk - 1] = idx;
#pragma unroll
                for (int j = Kk - 1; j > 0; --j) {
                    if (bd[j] > bd[j - 1]) {
                        float td = bd[j]; bd[j] = bd[j - 1]; bd[j - 1] = td;
                        int ti = bi[j]; bi[j] = bi[j - 1]; bi[j - 1] = ti;
                    }
                }
            }
        }
#pragma unroll
        for (int k = 0; k < Kk; ++k) s_idx[t][k] = bi[k];
    }
    for (int i = t; i < PPB * CIN / 4; i += THREADS) {
        int p = i / (CIN / 4), c4 = i % (CIN / 4);
        ((float4*)s_ctr[p])[c4] = ((const float4*)(xin + (size_t)(p0 + p) * CIN))[c4];
    }
    __syncthreads();
    for (int i = t; i < PPB * K2 * (CIN / 4); i += THREADS) {
        int c4 = i % (CIN / 4);
        int rest = i / (CIN / 4);
        int j = rest % K2, p = rest / K2;
        int bo = (p0 + p) / Nn;
        int i0 = s_idx[p][2 * j], i1 = s_idx[p][2 * j + 1];
        float4 n0 = ((const float4*)(xin + ((size_t)bo * Nn + i0) * CIN))[c4];
        float4 n1 = ((const float4*)(xin + ((size_t)bo * Nn + i1) * CIN))[c4];
        float4 ct = ((const float4*)s_ctr[p])[c4];
        float* dst = s_dnb2 + ((size_t)(p * K2 + j) * CIN) * 2 + 8 * c4;
        ((float4*)dst)[0] = make_float4(__fsub_rn(ct.x, n0.x), __fsub_rn(ct.x, n1.x),
                                        __fsub_rn(ct.y, n0.y), __fsub_rn(ct.y, n1.y));
        ((float4*)dst)[1] = make_float4(__fsub_rn(ct.z, n0.z), __fsub_rn(ct.z, n1.z),
                                        __fsub_rn(ct.w, n0.w), __fsub_rn(ct.w, n1.w));
    }
    __syncthreads();

    int o = t % COUT;
    int pbase = (t / COUT) * PT;
    const float* w1 = w + (size_t)o * 2 * CIN;
    const float* w2 = w1 + CIN;

    u64 acc2[PT][K2];
#pragma unroll
    for (int pt = 0; pt < PT; ++pt)
#pragma unroll
        for (int j = 0; j < K2; ++j) acc2[pt][j] = 0ull;

    constexpr int CH = (CIN < 8) ? CIN : 8;

    // Phase A: (ctr - nb_k) * w1, per-k FMA chain (packed across k-pairs)
#pragma unroll 1
    for (int cc = 0; cc < CIN; cc += CH) {
        u64 w1p[CH];
#pragma unroll
        for (int c4 = 0; c4 < CH / 4; ++c4) {
            float4 a = *(const float4*)(w1 + cc + c4 * 4);
            w1p[c4 * 4 + 0] = bc2(a.x); w1p[c4 * 4 + 1] = bc2(a.y);
            w1p[c4 * 4 + 2] = bc2(a.z); w1p[c4 * 4 + 3] = bc2(a.w);
        }
#pragma unroll
        for (int pt = 0; pt < PT; ++pt) {
            int p = pbase + pt;
#pragma unroll
            for (int j = 0; j < K2; ++j) {
                const ulonglong2* src =
                    (const ulonglong2*)(s_dnb2 + ((size_t)(p * K2 + j) * CIN + cc) * 2);
#pragma unroll
                for (int c2 = 0; c2 < CH / 2; ++c2) {
                    ulonglong2 v = src[c2];
                    acc2[pt][j] = ffma2(v.x, w1p[2 * c2 + 0], acc2[pt][j]);
                    acc2[pt][j] = ffma2(v.y, w1p[2 * c2 + 1], acc2[pt][j]);
                }
            }
        }
    }

    // Phase B: ctr * w2 appended per-k (per-chain rounding)
#pragma unroll 1
    for (int cc = 0; cc < CIN; cc += CH) {
        u64 w2p[CH];
#pragma unroll
        for (int c4 = 0; c4 < CH / 4; ++c4) {
            float4 a = *(const float4*)(w2 + cc + c4 * 4);
            w2p[c4 * 4 + 0] = bc2(a.x); w2p[c4 * 4 + 1] = bc2(a.y);
            w2p[c4 * 4 + 2] = bc2(a.z); w2p[c4 * 4 + 3] = bc2(a.w);
        }
#pragma unroll
        for (int pt = 0; pt < PT; ++pt) {
            int p = pbase + pt;
            u64 cp[CH];
#pragma unroll
            for (int c = 0; c < CH; ++c) cp[c] = bc2(s_ctr[p][cc + c]);
#pragma unroll
            for (int j = 0; j < K2; ++j)
#pragma unroll
                for (int c = 0; c < CH; ++c)
                    acc2[pt][j] = ffma2(cp[c], w2p[c], acc2[pt][j]);
        }
    }

    float scale = __fmul_rn(gg[o], __frsqrt_rn(__fadd_rn(vvar[o], 1e-5f)));
    float shift = __fsub_rn(bbias[o], __fmul_rn(mmean[o], scale));
#pragma unroll
    for (int pt = 0; pt < PT; ++pt) {
        float mx = -3.4e38f;
#pragma unroll
        for (int j = 0; j < K2; ++j) {
            float a, b2;
            upk2(acc2[pt][j], a, b2);
            mx = fmaxf(mx, fmaxf(a, b2));
        }
        float y = __fmaf_rn(mx, scale, shift);
        y = (y >= 0.f) ? y : __fmul_rn(0.2f, y);
        int gp = p0 + pbase + pt;
        int b = gp / Nn, n = gp % Nn;
        out[((size_t)b * 512 + coff + o) * Nn + n] = y;
        if (WXT) {
            xout[(size_t)gp * COUT + o] = y;
            s_yout[(pbase + pt) * COUT + o] = y;
        }
    }

    if (WXT) {
        __syncthreads();
        if (t < PPB) {
            float sum = 0.f;
#pragma unroll 1
            for (int c = 0; c < COUT; ++c) {
                float v = s_yout[t * COUT + c];
                sum = __fadd_rn(sum, __fmul_rn(v, v));
            }
            normout[p0 + t] = sum;
        }
    }
}

// ---------------------------------------------------------------------------
extern "C" void kernel_launch(void* const* d_in, const int* in_sizes, int n_in,
                              void* d_out, int out_size) {
    const float* x = (const float*)d_in[0];
    float* out = (float*)d_out;

    const float* w1 = (const float*)d_in[1];
    const float* g1 = (const float*)d_in[2];
    const float* b1 = (const float*)d_in[3];
    const float* m1 = (const float*)d_in[4];
    const float* v1 = (const float*)d_in[5];
    const float* w2 = (const float*)d_in[6];
    const float* g2 = (const float*)d_in[7];
    const float* b2 = (const float*)d_in[8];
    const float* m2 = (const float*)d_in[9];
    const float* v2 = (const float*)d_in[10];
    const float* w3 = (const float*)d_in[11];
    const float* g3 = (const float*)d_in[12];
    const float* b3 = (const float*)d_in[13];
    const float* m3 = (const float*)d_in[14];
    const float* v3 = (const float*)d_in[15];
    const float* w4 = (const float*)d_in[16];
    const float* g4 = (const float*)d_in[17];
    const float* b4 = (const float*)d_in[18];
    const float* m4 = (const float*)d_in[19];
    const float* v4 = (const float*)d_in[20];

    float* xa; float* xb_; float* na; float* nb;
    cudaGetSymbolAddress((void**)&xa, g_xTa);
    cudaGetSymbolAddress((void**)&xb_, g_xTb);
    cudaGetSymbolAddress((void**)&na, g_norma);
    cudaGetSymbolAddress((void**)&nb, g_normb);

    dim3 knn_grid((Nn + QB - 1) / QB, SEG, Bb);
    int tp_blocks = (NP + 255) / 256;

    // Layer 1: x (C=4) in buf A -> out[0:64), next-layer feats in buf B
    transpose_norm_kernel<<<tp_blocks, 256>>>(x, 4, 4 * Nn, xa, na);
    knn_part_kernel<4><<<knn_grid, TQ>>>(xa, na);
    edgeconv_kernel<4, 64, 2, true><<<NP / 8, 128>>>(w1, g1, b1, m1, v1, out, 0, xa, xb_, nb);

    // Layer 2: buf B (C=64) -> out[64:128), feats in buf A
    knn_part_kernel<64><<<knn_grid, TQ>>>(xb_, nb);
    edgeconv_kernel<64, 64, 2, true><<<NP / 8, 128>>>(w2, g2, b2, m2, v2, out, 64, xb_, xa, na);

    // Layer 3: buf A (C=64) -> out[128:256), feats in buf B
    knn_part_kernel<64><<<knn_grid, TQ>>>(xa, na);
    edgeconv_kernel<64, 128, 1, true><<<NP / 4, 128>>>(w3, g3, b3, m3, v3, out, 128, xa, xb_, nb);

    // Layer 4: buf B (C=128) -> out[256:512)
    knn_part_kernel<128><<<knn_grid, TQ>>>(xb_, nb);
    edgeconv_kernel<128, 256, 1, false><<<NP / 4, 256>>>(w4, g4, b4, m4, v4, out, 256, xb_, nullptr, nullptr);
}

// round 16
// speedup vs baseline: 1.2303x; 1.2303x over previous
#include <cuda_runtime.h>
#include <cstdint>
#include <cstddef>

// Problem constants
constexpr int Bb = 2;
constexpr int Nn = 10000;
constexpr int Kk = 20;
constexpr int NP = Bb * Nn;
constexpr int SEG = 8;
constexpr int SEGSZ = 1280;   // 7*1280 + 1040 = 10000 (last seg guarded)
constexpr int TQ = 128;
constexpr int QT = 2;         // queries per thread
constexpr int QB = TQ * QT;   // queries per block
constexpr int TM = 32;        // candidate tile
constexpr int PAIRS = TM / 2;
constexpr int PEND = 68;      // per-thread pending buffer (local mem)

// Scratch (device globals). g_xT ping-pong is for EdgeConv row gathers only;
// KNN reads features channel-major directly from x / out slices.
__device__ __align__(16) float g_xTa[(size_t)NP * 128];
__device__ __align__(16) float g_xTb[(size_t)NP * 128];
__device__ float g_norma[NP];
__device__ float g_normb[NP];
__device__ float g_pd[(size_t)NP * SEG * Kk];
__device__ int   g_pi[(size_t)NP * SEG * Kk];

using u64 = unsigned long long;
__device__ __forceinline__ u64 pk2(float lo, float hi) {
    u64 r; asm("mov.b64 %0,{%1,%2};" : "=l"(r) : "f"(lo), "f"(hi)); return r;
}
__device__ __forceinline__ u64 bc2(float v) { return pk2(v, v); }
__device__ __forceinline__ void upk2(u64 v, float& lo, float& hi) {
    asm("mov.b64 {%0,%1},%2;" : "=f"(lo), "=f"(hi) : "l"(v));
}
// Packed fp32 FMA / ADD (SASS FFMA2/FADD2): two independent IEEE fp32 ops.
__device__ __forceinline__ u64 ffma2(u64 a, u64 b, u64 c) {
    u64 d; asm("fma.rn.f32x2 %0,%1,%2,%3;" : "=l"(d) : "l"(a), "l"(b), "l"(c)); return d;
}
__device__ __forceinline__ u64 fadd2(u64 a, u64 b) {
    u64 d; asm("add.rn.f32x2 %0,%1,%2;" : "=l"(d) : "l"(a), "l"(b)); return d;
}
// Predicated store: no branch (no BSSY), no L1 wavefront when acc==0.
__device__ __forceinline__ void pstore(u64* addr, u64 val, unsigned acc) {
    asm volatile("{\n\t.reg .pred p;\n\tsetp.ne.u32 p, %0, 0;\n\t@p st.u64 [%1], %2;\n\t}"
        :: "r"(acc), "l"(addr), "l"(val) : "memory");
}

// ---------------------------------------------------------------------------
// Transpose (B,C,N) -> (B,N,C) + sq-norms — used only for the network input x.
// ---------------------------------------------------------------------------
__global__ void transpose_norm_kernel(const float* __restrict__ src, int C, int batchStride,
                                      float* __restrict__ xout, float* __restrict__ normout) {
    int p = blockIdx.x * blockDim.x + threadIdx.x;
    if (p >= NP) return;
    int b = p / Nn, n = p % Nn;
    const float* s = src + (size_t)b * batchStride + n;
    float* d = xout + (size_t)p * C;
    float sum = 0.f;
    for (int c = 0; c < C; ++c) {
        float v = s[(size_t)c * Nn];
        d[c] = v;
        sum = __fadd_rn(sum, __fmul_rn(v, v));
    }
    normout[p] = sum;
}

// ---------------------------------------------------------------------------
// KNN partial pass over one candidate segment. Features read CHANNEL-MAJOR
// (xc + b*bstride + c*Nn + n): query loads are 1 wavefront per LDG.32 and
// candidate staging is coalesced. Reference arithmetic exactly:
//   dot = ascending-c FMA chain;  pd = fsub(fsub(-xxq, -2*dot), xxm)
//   (packed: fma2(2,dot,negqn) [bitwise == since -2*dot exact] + add2(.,-mn))
// top-k LARGEST pd, tie -> lower index. Sorted smem lists; register threshold;
// predicated pending append; one batched drain per tile (FIFO + strict > +
// drain-time recheck => exact lax.top_k).
// ---------------------------------------------------------------------------
template <int C>
__global__ void __launch_bounds__(TQ) knn_part_kernel(const float* __restrict__ xc,
                                                      size_t bstride,
                                                      const float* __restrict__ norm) {
    __shared__ __align__(16) float ms2[TM * C];     // [pair][c][2]
    __shared__ u64 s_negmn2[PAIRS];                 // packed -norm pairs
    __shared__ float s_bd[QT][Kk][TQ];
    __shared__ unsigned short s_bi[QT][Kk][TQ];

    u64 pend[PEND];                                  // local mem (L1-resident)

    int b = blockIdx.z, seg = blockIdx.y;
    int t = threadIdx.x;
    const float* xcb = xc + (size_t)b * bstride;

    int q[QT]; bool act[QT]; int qi[QT]; u64 negqn2[QT]; float kth[QT];
#pragma unroll
    for (int s = 0; s < QT; ++s) {
        q[s] = blockIdx.x * QB + s * TQ + t;
        act[s] = q[s] < Nn;
        qi[s] = act[s] ? q[s] : 0;
        negqn2[s] = bc2(act[s] ? -norm[b * Nn + q[s]] : 0.f);
        kth[s] = act[s] ? -3.4e38f : 3.4e38f;   // inactive never accepts
#pragma unroll
        for (int k = 0; k < Kk; ++k) { s_bd[s][k][t] = -3.4e38f; s_bi[s][k][t] = 0; }
    }
    int cnt = 0;
    const u64 TWO2 = bc2(2.f);

    auto drain = [&]() {
#pragma unroll 1
        for (int i = 0; i < cnt; ++i) {
            float pdv, mf;
            upk2(pend[i], pdv, mf);
            unsigned m = __float_as_uint(mf);
            int s = (int)(m >> 15);
            unsigned short idx = (unsigned short)(m & 0x7FFFu);
            float kk = (s == 0) ? kth[0] : kth[1];
            if (pdv > kk) {
                int j = Kk - 1;
#pragma unroll 1
                while (j > 0) {
                    float prev = s_bd[s][j - 1][t];
                    if (pdv > prev) {
                        s_bd[s][j][t] = prev;
                        s_bi[s][j][t] = s_bi[s][j - 1][t];
                        --j;
                    } else break;
                }
                s_bd[s][j][t] = pdv;
                s_bi[s][j][t] = idx;
                if (s == 0) kth[0] = s_bd[0][Kk - 1][t];
                else        kth[1] = s_bd[1][Kk - 1][t];
            }
        }
        cnt = 0;
    };

    int mt0 = seg * SEGSZ;
    int mt1 = min(Nn, mt0 + SEGSZ);

#pragma unroll 1
    for (int mt = mt0; mt < mt1; mt += TM) {
        __syncthreads();
        // candidate staging from channel-major source: coalesced at fixed c.
        if (mt + TM <= Nn) {
#pragma unroll 1
            for (int i = t; i < C * (TM / 4); i += TQ) {
                int c = i >> 3;          // TM/4 == 8
                int j = i & 7;
                float4 v = *(const float4*)(xcb + (size_t)c * Nn + mt + 4 * j);
                int n0 = 4 * j;
                ms2[((n0 + 0) >> 1) * 2 * C + c * 2 + ((n0 + 0) & 1)] = v.x;
                ms2[((n0 + 1) >> 1) * 2 * C + c * 2 + ((n0 + 1) & 1)] = v.y;
                ms2[((n0 + 2) >> 1) * 2 * C + c * 2 + ((n0 + 2) & 1)] = v.z;
                ms2[((n0 + 3) >> 1) * 2 * C + c * 2 + ((n0 + 3) & 1)] = v.w;
            }
        } else {
#pragma unroll 1
            for (int i = t; i < C * TM; i += TQ) {
                int c = i >> 5;          // TM == 32
                int n0 = i & 31;
                int r = min(mt + n0, Nn - 1);
                ms2[(n0 >> 1) * 2 * C + c * 2 + (n0 & 1)] = xcb[(size_t)c * Nn + r];
            }
        }
        if (t < PAIRS)
            s_negmn2[t] = pk2(-norm[b * Nn + min(mt + 2 * t, Nn - 1)],
                              -norm[b * Nn + min(mt + 2 * t + 1, Nn - 1)]);
        __syncthreads();

        u64 part2[QT][PAIRS];
#pragma unroll
        for (int s = 0; s < QT; ++s)
#pragma unroll
            for (int p = 0; p < PAIRS; ++p) part2[s][p] = 0ull;

        constexpr int CH = (C < 8) ? C : 8;
#pragma unroll 1
        for (int cc = 0; cc < C; cc += CH) {
            u64 qv2[QT][CH];
#pragma unroll
            for (int c = 0; c < CH; ++c) {
                const float* col = xcb + (size_t)(cc + c) * Nn;
#pragma unroll
                for (int s = 0; s < QT; ++s)
                    qv2[s][c] = bc2(__ldg(col + qi[s]));
            }
#pragma unroll
            for (int p = 0; p < PAIRS; ++p) {
                const ulonglong2* src = (const ulonglong2*)(ms2 + p * 2 * C + 2 * cc);
#pragma unroll
                for (int c2 = 0; c2 < CH / 2; ++c2) {
                    ulonglong2 v = src[c2];
#pragma unroll
                    for (int s = 0; s < QT; ++s) {
                        part2[s][p] = ffma2(qv2[s][2 * c2 + 0], v.x, part2[s][p]);
                        part2[s][p] = ffma2(qv2[s][2 * c2 + 1], v.y, part2[s][p]);
                    }
                }
            }
        }

        // epilogue: predicated append (no branch, no store traffic on reject)
#pragma unroll
        for (int p = 0; p < PAIRS; ++p) {
            u64 nm = s_negmn2[p];
            int cidx = mt + 2 * p;
#pragma unroll
            for (int s = 0; s < QT; ++s) {
                u64 pd2 = fadd2(ffma2(TWO2, part2[s][p], negqn2[s]), nm);
                float p0, p1;
                upk2(pd2, p0, p1);
                unsigned m0 = ((unsigned)s << 15) | (unsigned)cidx;
                unsigned a0 = (p0 > kth[s] && cidx < mt1) ? 1u : 0u;
                pstore(pend + cnt, pk2(p0, __uint_as_float(m0)), a0);
                cnt += a0;
                unsigned a1 = (p1 > kth[s] && cidx + 1 < mt1) ? 1u : 0u;
                pstore(pend + cnt, pk2(p1, __uint_as_float(m0 + 1)), a1);
                cnt += a1;
            }
        }
        if (__ballot_sync(0xFFFFFFFFu, cnt > 0)) drain();
    }

#pragma unroll
    for (int s = 0; s < QT; ++s) {
        if (!act[s]) continue;
        size_t base = ((size_t)(b * Nn + q[s]) * SEG + seg) * Kk;
#pragma unroll
        for (int k = 0; k < Kk; ++k) {
            g_pd[base + k] = s_bd[s][k][t];
            g_pi[base + k] = (int)s_bi[s][k][t];
        }
    }
}

// ---------------------------------------------------------------------------
// EdgeConv + fused KNN-merge + fused transpose/norm for the next layer.
// xin != xout (ping-pong) => no same-launch RAW hazard.
// ---------------------------------------------------------------------------
template <int CIN, int COUT, int PG, bool WXT>
__global__ void edgeconv_kernel(const float* __restrict__ w,
                                const float* __restrict__ gg,
                                const float* __restrict__ bbias,
                                const float* __restrict__ mmean,
                                const float* __restrict__ vvar,
                                float* __restrict__ out, int coff,
                                const float* __restrict__ xin,
                                float* __restrict__ xout,
                                float* __restrict__ normout) {
    constexpr int PT = 4;
    constexpr int PPB = PT * PG;
    constexpr int THREADS = COUT * PG;
    constexpr int K2 = Kk / 2;

    __shared__ __align__(16) float s_dnb2[PPB * K2 * CIN * 2];  // [p][j][c][2]
    __shared__ __align__(16) float s_ctr[PPB][CIN];
    __shared__ int s_idx[PPB][Kk];
    __shared__ float s_yout[WXT ? PPB * COUT : 1];

    int p0 = blockIdx.x * PPB;
    int t = threadIdx.x;

    // fused merge: one thread per point combines SEG sorted 20-lists
    if (t < PPB) {
        float bd[Kk]; int bi[Kk];
#pragma unroll
        for (int i = 0; i < Kk; ++i) { bd[i] = -3.4e38f; bi[i] = 0; }
        size_t base = (size_t)(p0 + t) * SEG * Kk;
#pragma unroll 1
        for (int e = 0; e < SEG * Kk; ++e) {
            float pdv = g_pd[base + e];
            int idx = g_pi[base + e];
            if (pdv > bd[Kk - 1]) {
                bd[Kk - 1] = pdv; bi[Kk - 1] = idx;
#pragma unroll
                for (int j = Kk - 1; j > 0; --j) {
                    if (bd[j] > bd[j - 1]) {
                        float td = bd[j]; bd[j] = bd[j - 1]; bd[j - 1] = td;
                        int ti = bi[j]; bi[j] = bi[j - 1]; bi[j - 1] = ti;
                    }
                }
            }
        }
#pragma unroll
        for (int k = 0; k < Kk; ++k) s_idx[t][k] = bi[k];
    }
    for (int i = t; i < PPB * CIN / 4; i += THREADS) {
        int p = i / (CIN / 4), c4 = i % (CIN / 4);
        ((float4*)s_ctr[p])[c4] = ((const float4*)(xin + (size_t)(p0 + p) * CIN))[c4];
    }
    __syncthreads();
    for (int i = t; i < PPB * K2 * (CIN / 4); i += THREADS) {
        int c4 = i % (CIN / 4);
        int rest = i / (CIN / 4);
        int j = rest % K2, p = rest / K2;
        int bo = (p0 + p) / Nn;
        int i0 = s_idx[p][2 * j], i1 = s_idx[p][2 * j + 1];
        float4 n0 = ((const float4*)(xin + ((size_t)bo * Nn + i0) * CIN))[c4];
        float4 n1 = ((const float4*)(xin + ((size_t)bo * Nn + i1) * CIN))[c4];
        float4 ct = ((const float4*)s_ctr[p])[c4];
        float* dst = s_dnb2 + ((size_t)(p * K2 + j) * CIN) * 2 + 8 * c4;
        ((float4*)dst)[0] = make_float4(__fsub_rn(ct.x, n0.x), __fsub_rn(ct.x, n1.x),
                                        __fsub_rn(ct.y, n0.y), __fsub_rn(ct.y, n1.y));
        ((float4*)dst)[1] = make_float4(__fsub_rn(ct.z, n0.z), __fsub_rn(ct.z, n1.z),
                                        __fsub_rn(ct.w, n0.w), __fsub_rn(ct.w, n1.w));
    }
    __syncthreads();

    int o = t % COUT;
    int pbase = (t / COUT) * PT;
    const float* w1 = w + (size_t)o * 2 * CIN;
    const float* w2 = w1 + CIN;

    u64 acc2[PT][K2];
#pragma unroll
    for (int pt = 0; pt < PT; ++pt)
#pragma unroll
        for (int j = 0; j < K2; ++j) acc2[pt][j] = 0ull;

    constexpr int CH = (CIN < 8) ? CIN : 8;

    // Phase A: (ctr - nb_k) * w1, per-k FMA chain (packed across k-pairs)
#pragma unroll 1
    for (int cc = 0; cc < CIN; cc += CH) {
        u64 w1p[CH];
#pragma unroll
        for (int c4 = 0; c4 < CH / 4; ++c4) {
            float4 a = *(const float4*)(w1 + cc + c4 * 4);
            w1p[c4 * 4 + 0] = bc2(a.x); w1p[c4 * 4 + 1] = bc2(a.y);
            w1p[c4 * 4 + 2] = bc2(a.z); w1p[c4 * 4 + 3] = bc2(a.w);
        }
#pragma unroll
        for (int pt = 0; pt < PT; ++pt) {
            int p = pbase + pt;
#pragma unroll
            for (int j = 0; j < K2; ++j) {
                const ulonglong2* src =
                    (const ulonglong2*)(s_dnb2 + ((size_t)(p * K2 + j) * CIN + cc) * 2);
#pragma unroll
                for (int c2 = 0; c2 < CH / 2; ++c2) {
                    ulonglong2 v = src[c2];
                    acc2[pt][j] = ffma2(v.x, w1p[2 * c2 + 0], acc2[pt][j]);
                    acc2[pt][j] = ffma2(v.y, w1p[2 * c2 + 1], acc2[pt][j]);
                }
            }
        }
    }

    // Phase B: ctr * w2 appended per-k (per-chain rounding)
#pragma unroll 1
    for (int cc = 0; cc < CIN; cc += CH) {
        u64 w2p[CH];
#pragma unroll
        for (int c4 = 0; c4 < CH / 4; ++c4) {
            float4 a = *(const float4*)(w2 + cc + c4 * 4);
            w2p[c4 * 4 + 0] = bc2(a.x); w2p[c4 * 4 + 1] = bc2(a.y);
            w2p[c4 * 4 + 2] = bc2(a.z); w2p[c4 * 4 + 3] = bc2(a.w);
        }
#pragma unroll
        for (int pt = 0; pt < PT; ++pt) {
            int p = pbase + pt;
            u64 cp[CH];
#pragma unroll
            for (int c = 0; c < CH; ++c) cp[c] = bc2(s_ctr[p][cc + c]);
#pragma unroll
            for (int j = 0; j < K2; ++j)
#pragma unroll
                for (int c = 0; c < CH; ++c)
                    acc2[pt][j] = ffma2(cp[c], w2p[c], acc2[pt][j]);
        }
    }

    float scale = __fmul_rn(gg[o], __frsqrt_rn(__fadd_rn(vvar[o], 1e-5f)));
    float shift = __fsub_rn(bbias[o], __fmul_rn(mmean[o], scale));
#pragma unroll
    for (int pt = 0; pt < PT; ++pt) {
        float mx = -3.4e38f;
#pragma unroll
        for (int j = 0; j < K2; ++j) {
            float a, b2;
            upk2(acc2[pt][j], a, b2);
            mx = fmaxf(mx, fmaxf(a, b2));
        }
        float y = __fmaf_rn(mx, scale, shift);
        y = (y >= 0.f) ? y : __fmul_rn(0.2f, y);
        int gp = p0 + pbase + pt;
        int b = gp / Nn, n = gp % Nn;
        out[((size_t)b * 512 + coff + o) * Nn + n] = y;
        if (WXT) {
            xout[(size_t)gp * COUT + o] = y;
            s_yout[(pbase + pt) * COUT + o] = y;
        }
    }

    if (WXT) {
        __syncthreads();
        if (t < PPB) {
            float sum = 0.f;
#pragma unroll 1
            for (int c = 0; c < COUT; ++c) {
                float v = s_yout[t * COUT + c];
                sum = __fadd_rn(sum, __fmul_rn(v, v));
            }
            normout[p0 + t] = sum;
        }
    }
}

// ---------------------------------------------------------------------------
extern "C" void kernel_launch(void* const* d_in, const int* in_sizes, int n_in,
                              void* d_out, int out_size) {
    const float* x = (const float*)d_in[0];
    float* out = (float*)d_out;

    const float* w1 = (const float*)d_in[1];
    const float* g1 = (const float*)d_in[2];
    const float* b1 = (const float*)d_in[3];
    const float* m1 = (const float*)d_in[4];
    const float* v1 = (const float*)d_in[5];
    const float* w2 = (const float*)d_in[6];
    const float* g2 = (const float*)d_in[7];
    const float* b2 = (const float*)d_in[8];
    const float* m2 = (const float*)d_in[9];
    const float* v2 = (const float*)d_in[10];
    const float* w3 = (const float*)d_in[11];
    const float* g3 = (const float*)d_in[12];
    const float* b3 = (const float*)d_in[13];
    const float* m3 = (const float*)d_in[14];
    const float* v3 = (const float*)d_in[15];
    const float* w4 = (const float*)d_in[16];
    const float* g4 = (const float*)d_in[17];
    const float* b4 = (const float*)d_in[18];
    const float* m4 = (const float*)d_in[19];
    const float* v4 = (const float*)d_in[20];

    float* xa; float* xb_; float* na; float* nb;
    cudaGetSymbolAddress((void**)&xa, g_xTa);
    cudaGetSymbolAddress((void**)&xb_, g_xTb);
    cudaGetSymbolAddress((void**)&na, g_norma);
    cudaGetSymbolAddress((void**)&nb, g_normb);

    dim3 knn_grid((Nn + QB - 1) / QB, SEG, Bb);
    int tp_blocks = (NP + 255) / 256;
    size_t outBS = (size_t)512 * Nn;

    // Layer 1: x (C=4, channel-major already) -> out[0:64); feats/norms buf B
    transpose_norm_kernel<<<tp_blocks, 256>>>(x, 4, 4 * Nn, xa, na);
    knn_part_kernel<4><<<knn_grid, TQ>>>(x, (size_t)4 * Nn, na);
    edgeconv_kernel<4, 64, 2, true><<<NP / 8, 128>>>(w1, g1, b1, m1, v1, out, 0, xa, xb_, nb);

    // Layer 2: out[0:64) channel-major -> out[64:128); feats buf A
    knn_part_kernel<64><<<knn_grid, TQ>>>(out, outBS, nb);
    edgeconv_kernel<64, 64, 2, true><<<NP / 8, 128>>>(w2, g2, b2, m2, v2, out, 64, xb_, xa, na);

    // Layer 3: out[64:128) channel-major -> out[128:256); feats buf B
    knn_part_kernel<64><<<knn_grid, TQ>>>(out + (size_t)64 * Nn, outBS, na);
    edgeconv_kernel<64, 128, 1, true><<<NP / 4, 128>>>(w3, g3, b3, m3, v3, out, 128, xa, xb_, nb);

    // Layer 4: out[128:256) channel-major -> out[256:512)
    knn_part_kernel<128><<<knn_grid, TQ>>>(out + (size_t)128 * Nn, outBS, nb);
    edgeconv_kernel<128, 256, 1, false><<<NP / 4, 256>>>(w4, g4, b4, m4, v4, out, 256, xb_, nullptr, nullptr);
}